// round 13
// baseline (speedup 1.0000x reference)
#include <cuda_runtime.h>
#include <cuda_bf16.h>
#include <cstdint>

// PatchPlaneApproxLoss: fused 8x8 plane-fit surface normals + mean-abs-diff.
// B=8, H=479, W=639, P=8, FX=518.857, FY=519.469, EPS=1e-6.
// Shear-frame formulation (validated: rel_err 6e-6), packed f32x2 math.
// This round: 32x32 tile, 2 output pixels/thread (independent chains -> ILP
// against exposed latency), dynamic smem, fewer blocks.

#define Bn 8
#define Hh 479
#define Ww 639
#define TW 32
#define TH 32
#define TX 20   /* ceil(639/32) */
#define TY 15   /* ceil(479/32) */
#define NBLK (Bn * TX * TY)   /* 2400 */
#define NTHREADS 512
#define HALO_H (TH + 7)       /* 39 */
#define HALO_W (TW + 7)       /* 39, padded to 40 in smem */

#define INV_FX (1.0f / 518.857f)
#define INV_FY (1.0f / 519.469f)
#define EPSV   1e-6f

typedef unsigned long long u64;

// dynamic smem layout (bytes):
//   sD2  : u64        [HALO_H][40]      ->  12480
//   sHA  : ulonglong2 [HALO_H*TW]       ->  19968   {h1, ha}
//   sHB  : ulonglong2 [HALO_H*TW]       ->  19968   {haa, hd}
//   sHC  : u64        [HALO_H*TW]       ->   9984   had
#define OFF_D2 0
#define OFF_HA (OFF_D2 + HALO_H * 40 * 8)
#define OFF_HB (OFF_HA + HALO_H * TW * 16)
#define OFF_HC (OFF_HB + HALO_H * TW * 16)
#define SMEM_BYTES (OFF_HC + HALO_H * TW * 8)

__device__ __forceinline__ u64 pk2(float lo, float hi) {
    u64 r;
    asm("mov.b64 %0, {%1, %2};" : "=l"(r) : "f"(lo), "f"(hi));
    return r;
}
__device__ __forceinline__ void up2(u64 a, float& lo, float& hi) {
    asm("mov.b64 {%0, %1}, %2;" : "=f"(lo), "=f"(hi) : "l"(a));
}
__device__ __forceinline__ u64 add2(u64 a, u64 b) {
    u64 r;
    asm("add.rn.f32x2 %0, %1, %2;" : "=l"(r) : "l"(a), "l"(b));
    return r;
}
__device__ __forceinline__ u64 mul2(u64 a, u64 b) {
    u64 r;
    asm("mul.rn.f32x2 %0, %1, %2;" : "=l"(r) : "l"(a), "l"(b));
    return r;
}
__device__ __forceinline__ u64 fma2(u64 a, u64 b, u64 c) {
    u64 r;
    asm("fma.rn.f32x2 %0, %1, %2, %3;" : "=l"(r) : "l"(a), "l"(b), "l"(c));
    return r;
}
__device__ __forceinline__ u64 neg2(u64 a) { return a ^ 0x8000000080000000ULL; }

__device__ float g_partials[NBLK];
__device__ unsigned int g_counter = 0;

// Moments -> normal -> per-pixel packed |pred - gt| loss contribution.
__device__ __forceinline__ float solve_pix(
    u64 Sxx, u64 Sxy, u64 Sxz, u64 Syy, u64 Syz, u64 Szz,
    u64 Sx, u64 Sy, u64 Sz, float a0, float b0, u64 dcp)
{
    // epsilon: A' + EPS * S*S^T  (congruent to ref's A + EPS*I)
    float exx = EPSV * fmaf(a0, a0, 1.0f);
    float eyy = EPSV * fmaf(b0, b0, 1.0f);
    float exy = EPSV * (a0 * b0);
    float exz = -EPSV * a0;
    float eyz = -EPSV * b0;
    Sxx = add2(Sxx, pk2(exx, exx));
    Syy = add2(Syy, pk2(eyy, eyy));
    Szz = add2(Szz, pk2(EPSV, EPSV));
    Sxy = add2(Sxy, pk2(exy, exy));
    Sxz = add2(Sxz, pk2(exz, exz));
    Syz = add2(Syz, pk2(eyz, eyz));

    // m ∝ adj(A') * b'   (SPD => det>0; scale dies in normalize)
    u64 c00 = fma2(neg2(Syz), Syz, mul2(Syy, Szz));
    u64 c01 = fma2(neg2(Sxy), Szz, mul2(Sxz, Syz));
    u64 c02 = fma2(neg2(Sxz), Syy, mul2(Sxy, Syz));
    u64 c11 = fma2(neg2(Sxz), Sxz, mul2(Sxx, Szz));
    u64 c12 = fma2(neg2(Sxx), Syz, mul2(Sxy, Sxz));
    u64 c22 = fma2(neg2(Sxy), Sxy, mul2(Sxx, Syy));

    u64 mx = fma2(c02, Sz, fma2(c01, Sy, mul2(c00, Sx)));
    u64 my = fma2(c12, Sz, fma2(c11, Sy, mul2(c01, Sx)));
    u64 mz = fma2(c22, Sz, fma2(c12, Sy, mul2(c02, Sx)));

    // back-transform n = S^T m
    u64 a0p = pk2(a0, a0);
    u64 b0p = pk2(b0, b0);
    u64 n0 = mx;
    u64 n1 = my;
    u64 n2 = fma2(neg2(b0p), my, fma2(neg2(a0p), mx, mz));

    u64 s2 = fma2(n2, n2, fma2(n1, n1, mul2(n0, n0)));
    float s2a, s2b;
    up2(s2, s2a, s2b);
    u64 rn = pk2(rsqrtf(s2a), rsqrtf(s2b));
    n0 = mul2(n0, rn);
    n1 = mul2(n1, rn);
    n2 = mul2(n2, rn);

    // flip: sign(n . xyz) == sign(d * m_z); zero when depth <= 0
    float dc0, dc1, mz0, mz1;
    up2(dcp, dc0, dc1);
    up2(mz, mz0, mz1);
    float x0a, x0b, x1a, x1b, x2a, x2b;
    up2(n0, x0a, x0b);
    up2(n1, x1a, x1b);
    up2(n2, x2a, x2b);

    float f0 = (dc0 * mz0 > 0.0f) ? -1.0f : 1.0f;
    float f1 = (dc1 * mz1 > 0.0f) ? -1.0f : 1.0f;
    if (!(dc0 > 0.0f)) f0 = 0.0f;
    if (!(dc1 > 0.0f)) f1 = 0.0f;

    return fabsf(f0 * x0a - f1 * x0b)
         + fabsf(f0 * x1a - f1 * x1b)
         + fabsf(f0 * x2a - f1 * x2b);
}

__global__ __launch_bounds__(NTHREADS, 2)
void plane_loss_kernel(const float* __restrict__ pred, const float* __restrict__ gt,
                       float* __restrict__ out)
{
    extern __shared__ char smem_raw[];
    u64*        sD2 = (u64*)(smem_raw + OFF_D2);          // [HALO_H][40] packed {pred,gt}
    ulonglong2* sHA = (ulonglong2*)(smem_raw + OFF_HA);   // {h1, ha}
    ulonglong2* sHB = (ulonglong2*)(smem_raw + OFF_HB);   // {haa, hd}
    u64*        sHC = (u64*)(smem_raw + OFF_HC);          // had

    __shared__ float  sWarp[16];
    __shared__ double sDW[16];
    __shared__ bool   sLast;

    const int tid  = threadIdx.x;
    const int lane = tid & 31;
    const int wid  = tid >> 5;
    const int tc   = lane;
    const int tr0  = wid;          // first output row in tile
    const int tr1  = wid + 16;     // second output row
    const int bx   = blockIdx.x, by = blockIdx.y, bz = blockIdx.z;

    const int gor0 = by * TH + tr0;
    const int gor1 = by * TH + tr1;
    const int goc  = bx * TW + tc;
    const bool colok  = (goc < Ww);
    const bool valid0 = colok && (gor0 < Hh);
    const bool valid1 = colok && (gor1 < Hh);

    const float* img0 = pred + (size_t)bz * (Hh * Ww);
    const float* img1 = gt   + (size_t)bz * (Hh * Ww);

    // ---- halo load: warp-per-row, packed {pred, gt}, no integer division ----
    {
        const int gc0 = bx * TW + lane - 4;
        const int gc1 = gc0 + 32;
        for (int r = wid; r < HALO_H; r += 16) {
            int gr = by * TH + r - 4;
            bool rok = (gr >= 0) && (gr < Hh);
            float p0 = 0.f, q0 = 0.f;
            if (rok && gc0 >= 0 && gc0 < Ww) {
                p0 = img0[gr * Ww + gc0];
                q0 = img1[gr * Ww + gc0];
            }
            sD2[r * 40 + lane] = pk2(p0, q0);
            if (lane < 7) {
                float p1 = 0.f, q1 = 0.f;
                if (rok && gc1 < Ww) {
                    p1 = img0[gr * Ww + gc1];
                    q1 = img1[gr * Ww + gc1];
                }
                sD2[r * 40 + lane + 32] = pk2(p1, q1);
            }
        }
    }
    __syncthreads();

    // ---- horizontal 8-tap sums, packed, fixed weights da_k=(k-4)/FX ----
    // items: 39 rows x 32 cols = 1248 (both images at once)
    for (int e = tid; e < HALO_H * TW; e += NTHREADS) {
        int oc = e & 31;
        int r  = e >> 5;
        u64 h1 = 0, ha = 0, haa = 0, hd = 0, had = 0;
        #pragma unroll
        for (int k = 0; k < 8; ++k) {
            const float da = (float)(k - 4) * INV_FX;   // compile-time constant
            u64 d  = sD2[r * 40 + oc + k];
            u64 d2 = mul2(d, d);
            h1 = add2(h1, d2);
            hd = add2(hd, d);
            if (k != 4) {
                u64 dap = pk2(da, da);
                u64 t   = mul2(dap, d2);
                ha  = add2(ha, t);
                haa = fma2(dap, t, haa);
                had = fma2(dap, d, had);
            }
        }
        sHA[e] = make_ulonglong2(h1, ha);
        sHB[e] = make_ulonglong2(haa, hd);
        sHC[e] = had;
    }
    __syncthreads();

    // ---- vertical combine: TWO independent pixels per thread (ILP) ----
    float t_loss = 0.0f;
    {
        const ulonglong2* __restrict__ pA = &sHA[tr0 * TW + tc];
        const ulonglong2* __restrict__ pB = &sHB[tr0 * TW + tc];
        const u64*        __restrict__ pC = &sHC[tr0 * TW + tc];

        u64 aSxx = 0, aSxy = 0, aSxz = 0, aSyy = 0, aSyz = 0, aSzz = 0;
        u64 aSx = 0, aSy = 0, aSz = 0;
        u64 bSxx = 0, bSxy = 0, bSxz = 0, bSyy = 0, bSyz = 0, bSzz = 0;
        u64 bSx = 0, bSy = 0, bSz = 0;

        #pragma unroll
        for (int k = 0; k < 8; ++k) {
            const float db = (float)(k - 4) * INV_FY;   // compile-time constant
            // pixel A (row tr0): immediate offsets k*32
            ulonglong2 A0 = pA[k * TW];
            ulonglong2 B0 = pB[k * TW];
            u64 C0 = pC[k * TW];
            // pixel B (row tr1 = tr0+16): immediate offsets (k+16)*32
            ulonglong2 A1 = pA[(k + 16) * TW];
            ulonglong2 B1 = pB[(k + 16) * TW];
            u64 C1 = pC[(k + 16) * TW];

            aSzz = add2(aSzz, A0.x);  bSzz = add2(bSzz, A1.x);
            aSxz = add2(aSxz, A0.y);  bSxz = add2(bSxz, A1.y);
            aSxx = add2(aSxx, B0.x);  bSxx = add2(bSxx, B1.x);
            aSz  = add2(aSz,  B0.y);  bSz  = add2(bSz,  B1.y);
            aSx  = add2(aSx,  C0);    bSx  = add2(bSx,  C1);
            if (k != 4) {
                u64 dbp  = pk2(db, db);
                u64 db2p = pk2(db * db, db * db);
                aSyz = fma2(dbp,  A0.x, aSyz);  bSyz = fma2(dbp,  A1.x, bSyz);
                aSyy = fma2(db2p, A0.x, aSyy);  bSyy = fma2(db2p, A1.x, bSyy);
                aSxy = fma2(dbp,  A0.y, aSxy);  bSxy = fma2(dbp,  A1.y, bSxy);
                aSy  = fma2(dbp,  B0.y, aSy);   bSy  = fma2(dbp,  B1.y, bSy);
            }
        }

        const float a0 = ((float)goc - 319.5f) * INV_FX;
        if (valid0) {
            const float b0 = ((float)gor0 - 239.5f) * INV_FY;
            t_loss += solve_pix(aSxx, aSxy, aSxz, aSyy, aSyz, aSzz,
                                aSx, aSy, aSz, a0, b0,
                                sD2[(tr0 + 4) * 40 + tc + 4]);
        }
        if (valid1) {
            const float b0 = ((float)gor1 - 239.5f) * INV_FY;
            t_loss += solve_pix(bSxx, bSxy, bSxz, bSyy, bSyz, bSzz,
                                bSx, bSy, bSz, a0, b0,
                                sD2[(tr1 + 4) * 40 + tc + 4]);
        }
    }

    // ---- block reduction: warp shuffles + one smem stage ----
    float t = t_loss;
    #pragma unroll
    for (int o = 16; o > 0; o >>= 1)
        t += __shfl_down_sync(0xffffffffu, t, o);
    if (lane == 0) sWarp[wid] = t;
    __syncthreads();
    if (wid == 0) {
        float s = (lane < 16) ? sWarp[lane] : 0.0f;
        #pragma unroll
        for (int o = 8; o > 0; o >>= 1)
            s += __shfl_down_sync(0xffffffffu, s, o);
        if (lane == 0)
            g_partials[(bz * TY + by) * TX + bx] = s;
    }
    __syncthreads();

    // ---- last block performs the deterministic final reduction ----
    if (tid == 0) {
        __threadfence();
        unsigned int prev = atomicAdd(&g_counter, 1u);
        sLast = (prev == (unsigned)(NBLK - 1));
    }
    __syncthreads();

    if (sLast) {
        double acc = 0.0;
        for (int i = tid; i < NBLK; i += NTHREADS)
            acc += (double)g_partials[i];
        #pragma unroll
        for (int o = 16; o > 0; o >>= 1)
            acc += __shfl_down_sync(0xffffffffu, acc, o);
        if (lane == 0) sDW[wid] = acc;
        __syncthreads();
        if (wid == 0) {
            double s = (lane < 16) ? sDW[lane] : 0.0;
            #pragma unroll
            for (int o = 8; o > 0; o >>= 1)
                s += __shfl_down_sync(0xffffffffu, s, o);
            if (lane == 0) {
                const double cnt = (double)Bn * 3.0 * (double)Hh * (double)Ww;
                out[0] = (float)(s / cnt);
                g_counter = 0;   // reset for next graph replay
            }
        }
    }
}

extern "C" void kernel_launch(void* const* d_in, const int* in_sizes, int n_in,
                              void* d_out, int out_size)
{
    const float* pred = (const float*)d_in[0];
    const float* gt   = (const float*)d_in[1];
    float* out        = (float*)d_out;

    cudaFuncSetAttribute(plane_loss_kernel,
                         cudaFuncAttributeMaxDynamicSharedMemorySize, SMEM_BYTES);

    dim3 grid(TX, TY, Bn);
    plane_loss_kernel<<<grid, NTHREADS, SMEM_BYTES>>>(pred, gt, out);
}

// round 14
// speedup vs baseline: 1.1068x; 1.1068x over previous
#include <cuda_runtime.h>
#include <cuda_bf16.h>
#include <cstdint>

// PatchPlaneApproxLoss: fused 8x8 plane-fit surface normals + mean-abs-diff.
// B=8, H=479, W=639, P=8, FX=518.857, FY=519.469, EPS=1e-6.
// Shear-frame formulation (validated: rel_err 6e-6), packed f32x2 math.
// This round (diagnostic): R10 packed kernel with occupancy RESTORED to
// 4 CTAs/SM via __launch_bounds__(512,4) (regs capped at 32; small spills OK).
// Distinguishes "FFMA2 full-rate but occupancy-starved" vs "FFMA2 half-rate".

#define Bn 8
#define Hh 479
#define Ww 639
#define TW 32
#define TH 16
#define TX 20   /* ceil(639/32) */
#define TY 30   /* ceil(479/16) */
#define NBLK (Bn * TX * TY)   /* 4800 */
#define NTHREADS 512
#define HALO_H (TH + 7)       /* 23 */
#define HALO_W (TW + 7)       /* 39, padded to 40 in smem */

#define INV_FX (1.0f / 518.857f)
#define INV_FY (1.0f / 519.469f)
#define EPSV   1e-6f

typedef unsigned long long u64;

__device__ __forceinline__ u64 pk2(float lo, float hi) {
    u64 r;
    asm("mov.b64 %0, {%1, %2};" : "=l"(r) : "f"(lo), "f"(hi));
    return r;
}
__device__ __forceinline__ void up2(u64 a, float& lo, float& hi) {
    asm("mov.b64 {%0, %1}, %2;" : "=f"(lo), "=f"(hi) : "l"(a));
}
__device__ __forceinline__ u64 add2(u64 a, u64 b) {
    u64 r;
    asm("add.rn.f32x2 %0, %1, %2;" : "=l"(r) : "l"(a), "l"(b));
    return r;
}
__device__ __forceinline__ u64 mul2(u64 a, u64 b) {
    u64 r;
    asm("mul.rn.f32x2 %0, %1, %2;" : "=l"(r) : "l"(a), "l"(b));
    return r;
}
__device__ __forceinline__ u64 fma2(u64 a, u64 b, u64 c) {
    u64 r;
    asm("fma.rn.f32x2 %0, %1, %2, %3;" : "=l"(r) : "l"(a), "l"(b), "l"(c));
    return r;
}
__device__ __forceinline__ u64 neg2(u64 a) { return a ^ 0x8000000080000000ULL; }

__device__ float g_partials[NBLK];
__device__ unsigned int g_counter = 0;

__global__ __launch_bounds__(NTHREADS, 4)
void plane_loss_kernel(const float* __restrict__ pred, const float* __restrict__ gt,
                       float* __restrict__ out)
{
    __shared__ u64        sD2[HALO_H][40];       // packed {pred, gt} depth halo
    __shared__ ulonglong2 sHA[HALO_H * TW];      // {h1, ha}   packed pairs
    __shared__ ulonglong2 sHB[HALO_H * TW];      // {haa, hd}
    __shared__ u64        sHC[HALO_H * TW];      // had
    __shared__ float  sWarp[16];
    __shared__ double sDW[16];
    __shared__ bool   sLast;

    const int tid  = threadIdx.x;
    const int lane = tid & 31;
    const int wid  = tid >> 5;
    const int tc   = lane;
    const int tr   = wid;
    const int bx   = blockIdx.x, by = blockIdx.y, bz = blockIdx.z;

    const int gor = by * TH + tr;
    const int goc = bx * TW + tc;
    const bool valid = (gor < Hh) && (goc < Ww);

    const float* img0 = pred + (size_t)bz * (Hh * Ww);
    const float* img1 = gt   + (size_t)bz * (Hh * Ww);

    // ---- halo load: warp-per-row, packed {pred, gt}, no integer division ----
    {
        const int gc0 = bx * TW + lane - 4;
        const int gc1 = gc0 + 32;
        for (int r = wid; r < HALO_H; r += 16) {
            int gr = by * TH + r - 4;
            bool rok = (gr >= 0) && (gr < Hh);
            float p0 = 0.f, q0 = 0.f;
            if (rok && gc0 >= 0 && gc0 < Ww) {
                p0 = img0[gr * Ww + gc0];
                q0 = img1[gr * Ww + gc0];
            }
            sD2[r][lane] = pk2(p0, q0);
            if (lane < 7) {
                float p1 = 0.f, q1 = 0.f;
                if (rok && gc1 < Ww) {
                    p1 = img0[gr * Ww + gc1];
                    q1 = img1[gr * Ww + gc1];
                }
                sD2[r][lane + 32] = pk2(p1, q1);
            }
        }
    }
    __syncthreads();

    // ---- horizontal 8-tap sums, packed, fixed weights da_k=(k-4)/FX ----
    // items: 23 rows x 32 cols = 736 (both images at once)
    for (int e = tid; e < HALO_H * TW; e += NTHREADS) {
        int oc = e & 31;
        int r  = e >> 5;
        u64 h1 = 0, ha = 0, haa = 0, hd = 0, had = 0;
        #pragma unroll
        for (int k = 0; k < 8; ++k) {
            const float da = (float)(k - 4) * INV_FX;   // compile-time constant
            u64 d  = sD2[r][oc + k];
            u64 d2 = mul2(d, d);
            h1 = add2(h1, d2);
            hd = add2(hd, d);
            if (k != 4) {
                u64 dap = pk2(da, da);                   // 64-bit immediate
                u64 t   = mul2(dap, d2);
                ha  = add2(ha, t);
                haa = fma2(dap, t, haa);
                had = fma2(dap, d, had);
            }
        }
        sHA[e] = make_ulonglong2(h1, ha);
        sHB[e] = make_ulonglong2(haa, hd);
        sHC[e] = had;
    }
    __syncthreads();

    // ---- vertical combine -> shear-frame moments -> adjugate solve (packed) ----
    float t_loss = 0.0f;
    if (valid) {
        const ulonglong2* __restrict__ pA = &sHA[tr * TW + tc];
        const ulonglong2* __restrict__ pB = &sHB[tr * TW + tc];
        const u64*        __restrict__ pC = &sHC[tr * TW + tc];

        u64 Sxx = 0, Sxy = 0, Sxz = 0, Syy = 0, Syz = 0, Szz = 0;
        u64 Sx = 0, Sy = 0, Sz = 0;
        #pragma unroll
        for (int k = 0; k < 8; ++k) {
            const float db = (float)(k - 4) * INV_FY;   // compile-time constant
            ulonglong2 A = pA[k * TW];    // {h1, ha}
            ulonglong2 B = pB[k * TW];    // {haa, hd}
            Szz = add2(Szz, A.x);
            Sxz = add2(Sxz, A.y);
            Sxx = add2(Sxx, B.x);
            Sz  = add2(Sz,  B.y);
            Sx  = add2(Sx,  pC[k * TW]);
            if (k != 4) {
                u64 dbp  = pk2(db, db);
                u64 db2p = pk2(db * db, db * db);
                Syz = fma2(dbp,  A.x, Syz);
                Syy = fma2(db2p, A.x, Syy);
                Sxy = fma2(dbp,  A.y, Sxy);
                Sy  = fma2(dbp,  B.y, Sy);
            }
        }

        // epsilon: A' + EPS * S*S^T  (congruent to ref's A + EPS*I)
        const float a0 = ((float)goc - 319.5f) * INV_FX;
        const float b0 = ((float)gor - 239.5f) * INV_FY;
        {
            float exx = EPSV * fmaf(a0, a0, 1.0f);
            float eyy = EPSV * fmaf(b0, b0, 1.0f);
            float exy = EPSV * (a0 * b0);
            float exz = -EPSV * a0;
            float eyz = -EPSV * b0;
            Sxx = add2(Sxx, pk2(exx, exx));
            Syy = add2(Syy, pk2(eyy, eyy));
            Szz = add2(Szz, pk2(EPSV, EPSV));
            Sxy = add2(Sxy, pk2(exy, exy));
            Sxz = add2(Sxz, pk2(exz, exz));
            Syz = add2(Syz, pk2(eyz, eyz));
        }

        // m ∝ adj(A') * b'   (SPD => det>0; scale dies in normalize)
        u64 c00 = fma2(neg2(Syz), Syz, mul2(Syy, Szz));
        u64 c01 = fma2(neg2(Sxy), Szz, mul2(Sxz, Syz));
        u64 c02 = fma2(neg2(Sxz), Syy, mul2(Sxy, Syz));
        u64 c11 = fma2(neg2(Sxz), Sxz, mul2(Sxx, Szz));
        u64 c12 = fma2(neg2(Sxx), Syz, mul2(Sxy, Sxz));
        u64 c22 = fma2(neg2(Sxy), Sxy, mul2(Sxx, Syy));

        u64 mx = fma2(c02, Sz, fma2(c01, Sy, mul2(c00, Sx)));
        u64 my = fma2(c12, Sz, fma2(c11, Sy, mul2(c01, Sx)));
        u64 mz = fma2(c22, Sz, fma2(c12, Sy, mul2(c02, Sx)));

        // back-transform n = S^T m  (single negation of the shear pair)
        u64 a0p = pk2(-a0, -a0);
        u64 b0p = pk2(-b0, -b0);
        u64 n0 = mx;
        u64 n1 = my;
        u64 n2 = fma2(b0p, my, fma2(a0p, mx, mz));

        u64 s2 = fma2(n2, n2, fma2(n1, n1, mul2(n0, n0)));
        float s2a, s2b;
        up2(s2, s2a, s2b);
        u64 rn = pk2(rsqrtf(s2a), rsqrtf(s2b));
        n0 = mul2(n0, rn);
        n1 = mul2(n1, rn);
        n2 = mul2(n2, rn);

        // flip: sign(n . xyz) == sign(d * m_z); zero when depth <= 0
        float dc0, dc1, mz0, mz1;
        up2(sD2[tr + 4][tc + 4], dc0, dc1);
        up2(mz, mz0, mz1);
        float x0a, x0b, x1a, x1b, x2a, x2b;
        up2(n0, x0a, x0b);
        up2(n1, x1a, x1b);
        up2(n2, x2a, x2b);

        float f0 = (dc0 * mz0 > 0.0f) ? -1.0f : 1.0f;
        float f1 = (dc1 * mz1 > 0.0f) ? -1.0f : 1.0f;
        if (!(dc0 > 0.0f)) f0 = 0.0f;
        if (!(dc1 > 0.0f)) f1 = 0.0f;

        t_loss = fabsf(f0 * x0a - f1 * x0b)
               + fabsf(f0 * x1a - f1 * x1b)
               + fabsf(f0 * x2a - f1 * x2b);
    }

    // ---- block reduction: warp shuffles + one smem stage ----
    float t = t_loss;
    #pragma unroll
    for (int o = 16; o > 0; o >>= 1)
        t += __shfl_down_sync(0xffffffffu, t, o);
    if (lane == 0) sWarp[wid] = t;
    __syncthreads();
    if (wid == 0) {
        float s = (lane < 16) ? sWarp[lane] : 0.0f;
        #pragma unroll
        for (int o = 8; o > 0; o >>= 1)
            s += __shfl_down_sync(0xffffffffu, s, o);
        if (lane == 0)
            g_partials[(bz * TY + by) * TX + bx] = s;
    }
    __syncthreads();

    // ---- last block performs the deterministic final reduction ----
    if (tid == 0) {
        __threadfence();
        unsigned int prev = atomicAdd(&g_counter, 1u);
        sLast = (prev == (unsigned)(NBLK - 1));
    }
    __syncthreads();

    if (sLast) {
        double acc = 0.0;
        for (int i = tid; i < NBLK; i += NTHREADS)
            acc += (double)g_partials[i];
        #pragma unroll
        for (int o = 16; o > 0; o >>= 1)
            acc += __shfl_down_sync(0xffffffffu, acc, o);
        if (lane == 0) sDW[wid] = acc;
        __syncthreads();
        if (wid == 0) {
            double s = (lane < 16) ? sDW[lane] : 0.0;
            #pragma unroll
            for (int o = 8; o > 0; o >>= 1)
                s += __shfl_down_sync(0xffffffffu, s, o);
            if (lane == 0) {
                const double cnt = (double)Bn * 3.0 * (double)Hh * (double)Ww;
                out[0] = (float)(s / cnt);
                g_counter = 0;   // reset for next graph replay
            }
        }
    }
}

extern "C" void kernel_launch(void* const* d_in, const int* in_sizes, int n_in,
                              void* d_out, int out_size)
{
    const float* pred = (const float*)d_in[0];
    const float* gt   = (const float*)d_in[1];
    float* out        = (float*)d_out;

    dim3 grid(TX, TY, Bn);
    plane_loss_kernel<<<grid, NTHREADS>>>(pred, gt, out);
}

// round 17
// speedup vs baseline: 1.1344x; 1.0250x over previous
#include <cuda_runtime.h>
#include <cuda_bf16.h>
#include <cstdint>

// PatchPlaneApproxLoss: fused 8x8 plane-fit surface normals + mean-abs-diff.
// B=8, H=479, W=639, P=8, FX=518.857, FY=519.469, EPS=1e-6.
// Shear-frame formulation, packed f32x2 math, 4 CTAs/SM (validated R14: 57.8us).
// This round: symmetric-pair horizontal pass (-35% fma insts there) and
// interior-block fast-path halo load. Vertical/solve byte-identical to R14.

#define Bn 8
#define Hh 479
#define Ww 639
#define TW 32
#define TH 16
#define TX 20   /* ceil(639/32) */
#define TY 30   /* ceil(479/16) */
#define NBLK (Bn * TX * TY)   /* 4800 */
#define NTHREADS 512
#define HALO_H (TH + 7)       /* 23 */
#define HALO_W (TW + 7)       /* 39, padded to 40 in smem */

#define INV_FX (1.0f / 518.857f)
#define INV_FY (1.0f / 519.469f)
#define EPSV   1e-6f

typedef unsigned long long u64;

__device__ __forceinline__ u64 pk2(float lo, float hi) {
    u64 r;
    asm("mov.b64 %0, {%1, %2};" : "=l"(r) : "f"(lo), "f"(hi));
    return r;
}
__device__ __forceinline__ void up2(u64 a, float& lo, float& hi) {
    asm("mov.b64 {%0, %1}, %2;" : "=f"(lo), "=f"(hi) : "l"(a));
}
__device__ __forceinline__ u64 add2(u64 a, u64 b) {
    u64 r;
    asm("add.rn.f32x2 %0, %1, %2;" : "=l"(r) : "l"(a), "l"(b));
    return r;
}
__device__ __forceinline__ u64 mul2(u64 a, u64 b) {
    u64 r;
    asm("mul.rn.f32x2 %0, %1, %2;" : "=l"(r) : "l"(a), "l"(b));
    return r;
}
__device__ __forceinline__ u64 fma2(u64 a, u64 b, u64 c) {
    u64 r;
    asm("fma.rn.f32x2 %0, %1, %2, %3;" : "=l"(r) : "l"(a), "l"(b), "l"(c));
    return r;
}
__device__ __forceinline__ u64 neg2(u64 a) { return a ^ 0x8000000080000000ULL; }
__device__ __forceinline__ u64 sub2(u64 a, u64 b) { return add2(a, neg2(b)); }

__device__ float g_partials[NBLK];
__device__ unsigned int g_counter = 0;

__global__ __launch_bounds__(NTHREADS, 4)
void plane_loss_kernel(const float* __restrict__ pred, const float* __restrict__ gt,
                       float* __restrict__ out)
{
    __shared__ u64        sD2[HALO_H][40];       // packed {pred, gt} depth halo
    __shared__ ulonglong2 sHA[HALO_H * TW];      // {h1, ha}   packed pairs
    __shared__ ulonglong2 sHB[HALO_H * TW];      // {haa, hd}
    __shared__ u64        sHC[HALO_H * TW];      // had
    __shared__ float  sWarp[16];
    __shared__ double sDW[16];
    __shared__ bool   sLast;

    const int tid  = threadIdx.x;
    const int lane = tid & 31;
    const int wid  = tid >> 5;
    const int tc   = lane;
    const int tr   = wid;
    const int bx   = blockIdx.x, by = blockIdx.y, bz = blockIdx.z;

    const int gor = by * TH + tr;
    const int goc = bx * TW + tc;
    const bool valid = (gor < Hh) && (goc < Ww);

    const float* img0 = pred + (size_t)bz * (Hh * Ww);
    const float* img1 = gt   + (size_t)bz * (Hh * Ww);

    // ---- halo load: warp-per-row, packed {pred, gt} ----
    // Interior blocks (84%) take the predicate-free fast path.
    const bool interior = (bx >= 1) && (bx <= 18) && (by >= 1) && (by <= 28);
    if (interior) {
        const int base = (by * TH - 4) * Ww + bx * TW - 4 + lane;
        for (int r = wid; r < HALO_H; r += 16) {
            const int o = base + r * Ww;
            float p0 = img0[o];
            float q0 = img1[o];
            sD2[r][lane] = pk2(p0, q0);
            if (lane < 7) {
                float p1 = img0[o + 32];
                float q1 = img1[o + 32];
                sD2[r][lane + 32] = pk2(p1, q1);
            }
        }
    } else {
        const int gc0 = bx * TW + lane - 4;
        const int gc1 = gc0 + 32;
        for (int r = wid; r < HALO_H; r += 16) {
            int gr = by * TH + r - 4;
            bool rok = (gr >= 0) && (gr < Hh);
            float p0 = 0.f, q0 = 0.f;
            if (rok && gc0 >= 0 && gc0 < Ww) {
                p0 = img0[gr * Ww + gc0];
                q0 = img1[gr * Ww + gc0];
            }
            sD2[r][lane] = pk2(p0, q0);
            if (lane < 7) {
                float p1 = 0.f, q1 = 0.f;
                if (rok && gc1 < Ww) {
                    p1 = img0[gr * Ww + gc1];
                    q1 = img1[gr * Ww + gc1];
                }
                sD2[r][lane + 32] = pk2(p1, q1);
            }
        }
    }
    __syncthreads();

    // ---- horizontal 8-tap sums, symmetric-pair form ----
    // offsets k-4 in {-4..3}: center k=4, single k=0 (delta=-4/FX),
    // pairs t=1..3: (4-t, 4+t) share |delta| -> sum/diff combos.
    for (int e = tid; e < HALO_H * TW; e += NTHREADS) {
        int oc = e & 31;
        int r  = e >> 5;
        const u64* row = &sD2[r][oc];

        // center tap k=4
        u64 d4 = row[4];
        u64 h1 = mul2(d4, d4);
        u64 hd = d4;

        // single tap k=0, delta = -4/FX
        const u64 c0  = pk2(-4.0f * INV_FX, -4.0f * INV_FX);
        u64 d0 = row[0];
        u64 m0 = mul2(d0, d0);
        h1 = add2(h1, m0);
        hd = add2(hd, d0);
        u64 t0  = mul2(c0, m0);
        u64 ha  = t0;
        u64 haa = mul2(c0, t0);
        u64 had = mul2(c0, d0);

        // symmetric pairs t = 1..3
        #pragma unroll
        for (int t = 1; t <= 3; ++t) {
            const float dv  = (float)t * INV_FX;
            const u64 ct  = pk2(dv, dv);
            const u64 ct2 = pk2(dv * dv, dv * dv);
            u64 dm = row[4 - t];
            u64 dp = row[4 + t];
            u64 mm = mul2(dm, dm);
            u64 mp = mul2(dp, dp);
            u64 s  = add2(mp, mm);
            u64 q  = sub2(mp, mm);
            u64 sd = add2(dp, dm);
            u64 qd = sub2(dp, dm);
            h1  = add2(h1, s);
            hd  = add2(hd, sd);
            ha  = fma2(ct,  q,  ha);
            haa = fma2(ct2, s,  haa);
            had = fma2(ct,  qd, had);
        }

        sHA[e] = make_ulonglong2(h1, ha);
        sHB[e] = make_ulonglong2(haa, hd);
        sHC[e] = had;
    }
    __syncthreads();

    // ---- vertical combine -> shear-frame moments -> adjugate solve (packed) ----
    float t_loss = 0.0f;
    if (valid) {
        const ulonglong2* __restrict__ pA = &sHA[tr * TW + tc];
        const ulonglong2* __restrict__ pB = &sHB[tr * TW + tc];
        const u64*        __restrict__ pC = &sHC[tr * TW + tc];

        u64 Sxx = 0, Sxy = 0, Sxz = 0, Syy = 0, Syz = 0, Szz = 0;
        u64 Sx = 0, Sy = 0, Sz = 0;
        #pragma unroll
        for (int k = 0; k < 8; ++k) {
            const float db = (float)(k - 4) * INV_FY;   // compile-time constant
            ulonglong2 A = pA[k * TW];    // {h1, ha}
            ulonglong2 B = pB[k * TW];    // {haa, hd}
            Szz = add2(Szz, A.x);
            Sxz = add2(Sxz, A.y);
            Sxx = add2(Sxx, B.x);
            Sz  = add2(Sz,  B.y);
            Sx  = add2(Sx,  pC[k * TW]);
            if (k != 4) {
                u64 dbp  = pk2(db, db);
                u64 db2p = pk2(db * db, db * db);
                Syz = fma2(dbp,  A.x, Syz);
                Syy = fma2(db2p, A.x, Syy);
                Sxy = fma2(dbp,  A.y, Sxy);
                Sy  = fma2(dbp,  B.y, Sy);
            }
        }

        // epsilon: A' + EPS * S*S^T  (congruent to ref's A + EPS*I)
        const float a0 = ((float)goc - 319.5f) * INV_FX;
        const float b0 = ((float)gor - 239.5f) * INV_FY;
        {
            float exx = EPSV * fmaf(a0, a0, 1.0f);
            float eyy = EPSV * fmaf(b0, b0, 1.0f);
            float exy = EPSV * (a0 * b0);
            float exz = -EPSV * a0;
            float eyz = -EPSV * b0;
            Sxx = add2(Sxx, pk2(exx, exx));
            Syy = add2(Syy, pk2(eyy, eyy));
            Szz = add2(Szz, pk2(EPSV, EPSV));
            Sxy = add2(Sxy, pk2(exy, exy));
            Sxz = add2(Sxz, pk2(exz, exz));
            Syz = add2(Syz, pk2(eyz, eyz));
        }

        // m ∝ adj(A') * b'   (SPD => det>0; scale dies in normalize)
        u64 c00 = fma2(neg2(Syz), Syz, mul2(Syy, Szz));
        u64 c01 = fma2(neg2(Sxy), Szz, mul2(Sxz, Syz));
        u64 c02 = fma2(neg2(Sxz), Syy, mul2(Sxy, Syz));
        u64 c11 = fma2(neg2(Sxz), Sxz, mul2(Sxx, Szz));
        u64 c12 = fma2(neg2(Sxx), Syz, mul2(Sxy, Sxz));
        u64 c22 = fma2(neg2(Sxy), Sxy, mul2(Sxx, Syy));

        u64 mx = fma2(c02, Sz, fma2(c01, Sy, mul2(c00, Sx)));
        u64 my = fma2(c12, Sz, fma2(c11, Sy, mul2(c01, Sx)));
        u64 mz = fma2(c22, Sz, fma2(c12, Sy, mul2(c02, Sx)));

        // back-transform n = S^T m  (single negation of the shear pair)
        u64 a0p = pk2(-a0, -a0);
        u64 b0p = pk2(-b0, -b0);
        u64 n0 = mx;
        u64 n1 = my;
        u64 n2 = fma2(b0p, my, fma2(a0p, mx, mz));

        u64 s2 = fma2(n2, n2, fma2(n1, n1, mul2(n0, n0)));
        float s2a, s2b;
        up2(s2, s2a, s2b);
        u64 rn = pk2(rsqrtf(s2a), rsqrtf(s2b));
        n0 = mul2(n0, rn);
        n1 = mul2(n1, rn);
        n2 = mul2(n2, rn);

        // flip: sign(n . xyz) == sign(d * m_z); zero when depth <= 0
        float dc0, dc1, mz0, mz1;
        up2(sD2[tr + 4][tc + 4], dc0, dc1);
        up2(mz, mz0, mz1);
        float x0a, x0b, x1a, x1b, x2a, x2b;
        up2(n0, x0a, x0b);
        up2(n1, x1a, x1b);
        up2(n2, x2a, x2b);

        float f0 = (dc0 * mz0 > 0.0f) ? -1.0f : 1.0f;
        float f1 = (dc1 * mz1 > 0.0f) ? -1.0f : 1.0f;
        if (!(dc0 > 0.0f)) f0 = 0.0f;
        if (!(dc1 > 0.0f)) f1 = 0.0f;

        t_loss = fabsf(f0 * x0a - f1 * x0b)
               + fabsf(f0 * x1a - f1 * x1b)
               + fabsf(f0 * x2a - f1 * x2b);
    }

    // ---- block reduction: warp shuffles + one smem stage ----
    float t = t_loss;
    #pragma unroll
    for (int o = 16; o > 0; o >>= 1)
        t += __shfl_down_sync(0xffffffffu, t, o);
    if (lane == 0) sWarp[wid] = t;
    __syncthreads();
    if (wid == 0) {
        float s = (lane < 16) ? sWarp[lane] : 0.0f;
        #pragma unroll
        for (int o = 8; o > 0; o >>= 1)
            s += __shfl_down_sync(0xffffffffu, s, o);
        if (lane == 0)
            g_partials[(bz * TY + by) * TX + bx] = s;
    }
    __syncthreads();

    // ---- last block performs the deterministic final reduction ----
    if (tid == 0) {
        __threadfence();
        unsigned int prev = atomicAdd(&g_counter, 1u);
        sLast = (prev == (unsigned)(NBLK - 1));
    }
    __syncthreads();

    if (sLast) {
        double acc = 0.0;
        for (int i = tid; i < NBLK; i += NTHREADS)
            acc += (double)g_partials[i];
        #pragma unroll
        for (int o = 16; o > 0; o >>= 1)
            acc += __shfl_down_sync(0xffffffffu, acc, o);
        if (lane == 0) sDW[wid] = acc;
        __syncthreads();
        if (wid == 0) {
            double s = (lane < 16) ? sDW[lane] : 0.0;
            #pragma unroll
            for (int o = 8; o > 0; o >>= 1)
                s += __shfl_down_sync(0xffffffffu, s, o);
            if (lane == 0) {
                const double cnt = (double)Bn * 3.0 * (double)Hh * (double)Ww;
                out[0] = (float)(s / cnt);
                g_counter = 0;   // reset for next graph replay
            }
        }
    }
}

extern "C" void kernel_launch(void* const* d_in, const int* in_sizes, int n_in,
                              void* d_out, int out_size)
{
    const float* pred = (const float*)d_in[0];
    const float* gt   = (const float*)d_in[1];
    float* out        = (float*)d_out;

    dim3 grid(TX, TY, Bn);
    plane_loss_kernel<<<grid, NTHREADS>>>(pred, gt, out);
}